// round 2
// baseline (speedup 1.0000x reference)
#include <cuda_runtime.h>
#include <cstdint>

#define B_SZ  16384
#define IN_SZ 768
#define H_SZ  1024
#define R_SZ  64

// ---------------- scratch (__device__ globals; allocation-free contract) ----------------
__device__ float g_T[(size_t)B_SZ * 512];               // packed [P_g | Q_g] per gate, 32 MB
__device__ float g_G[(size_t)4 * B_SZ * H_SZ];          // gate preactivations, 256 MB
__device__ float g_W1x[IN_SZ * 256];                    // packed [Wu_f|Wu_i|Wu_c|Wu_o]
__device__ float g_W1h[H_SZ * 256];                     // packed [Uu_f|Uu_i|Uu_c|Uu_o]
__device__ float g_W2[4 * 128 * H_SZ];                  // per gate: rows 0..63 = Wg, 64..127 = Ug
__device__ float g_aw[4][IN_SZ];                        // W_dia - diag_w_g
__device__ float g_bu[4][H_SZ];                         // U_dia - diag_u_g

// ---------------- f32x2 helpers (sm_103a packed FMA) ----------------
__device__ __forceinline__ unsigned long long ffma2(unsigned long long a, unsigned long long b,
                                                    unsigned long long c) {
    unsigned long long d;
    asm("fma.rn.f32x2 %0, %1, %2, %3;" : "=l"(d) : "l"(a), "l"(b), "l"(c));
    return d;
}
__device__ __forceinline__ unsigned long long pack2(float v) {
    unsigned long long d;
    asm("mov.b64 %0, {%1, %1};" : "=l"(d) : "f"(v));
    return d;
}
__device__ __forceinline__ void unpack2(unsigned long long v, float& a, float& b) {
    asm("mov.b64 {%0, %1}, %2;" : "=f"(a), "=f"(b) : "l"(v));
}

__device__ __forceinline__ const float* sel4(int g, const float* a, const float* b,
                                             const float* c, const float* d) {
    return g == 0 ? a : g == 1 ? b : g == 2 ? c : d;
}

// ---------------- prep kernels ----------------
__global__ void prep_pack1(const float* __restrict__ Wu_f, const float* __restrict__ Wu_i,
                           const float* __restrict__ Wu_c, const float* __restrict__ Wu_o,
                           const float* __restrict__ Uu_f, const float* __restrict__ Uu_i,
                           const float* __restrict__ Uu_c, const float* __restrict__ Uu_o) {
    int idx = blockIdx.x * blockDim.x + threadIdx.x;
    if (idx < H_SZ * 256) {
        int k = idx >> 8, n = idx & 255, g = n >> 6, r = n & 63;
        const float* U = sel4(g, Uu_f, Uu_i, Uu_c, Uu_o);
        g_W1h[idx] = U[k * R_SZ + r];
    }
    if (idx < IN_SZ * 256) {
        int k = idx >> 8, n = idx & 255, g = n >> 6, r = n & 63;
        const float* W = sel4(g, Wu_f, Wu_i, Wu_c, Wu_o);
        g_W1x[idx] = W[k * R_SZ + r];
    }
}

__global__ void prep_pack2(const float* __restrict__ Wf, const float* __restrict__ Wi,
                           const float* __restrict__ Wc, const float* __restrict__ Wo,
                           const float* __restrict__ Uf, const float* __restrict__ Ui,
                           const float* __restrict__ Uc, const float* __restrict__ Uo) {
    int idx = blockIdx.x * blockDim.x + threadIdx.x;  // 4*128*1024
    if (idx >= 4 * 128 * H_SZ) return;
    int g = idx >> 17;
    int rest = idx & ((1 << 17) - 1);
    int r = rest >> 10;
    int j = rest & 1023;
    const float* Wg = sel4(g, Wf, Wi, Wc, Wo);
    const float* Ug = sel4(g, Uf, Ui, Uc, Uo);
    g_W2[idx] = (r < 64) ? Wg[r * H_SZ + j] : Ug[(r - 64) * H_SZ + j];
}

__global__ void prep_diag(const float* __restrict__ Wu_f, const float* __restrict__ Wu_i,
                          const float* __restrict__ Wu_c, const float* __restrict__ Wu_o,
                          const float* __restrict__ Uu_f, const float* __restrict__ Uu_i,
                          const float* __restrict__ Uu_c, const float* __restrict__ Uu_o,
                          const float* __restrict__ Wf, const float* __restrict__ Wi,
                          const float* __restrict__ Wc, const float* __restrict__ Wo,
                          const float* __restrict__ Uf, const float* __restrict__ Ui,
                          const float* __restrict__ Uc, const float* __restrict__ Uo,
                          const float* __restrict__ W_dia, const float* __restrict__ U_dia) {
    int t = blockIdx.x * blockDim.x + threadIdx.x;  // 4*1024
    if (t >= 4 * H_SZ) return;
    int g = t >> 10, j = t & 1023;
    const float* Uu = sel4(g, Uu_f, Uu_i, Uu_c, Uu_o);
    const float* Ug = sel4(g, Uf, Ui, Uc, Uo);
    float s = 0.f;
#pragma unroll 8
    for (int r = 0; r < R_SZ; ++r) s += Uu[j * R_SZ + r] * Ug[r * H_SZ + j];
    g_bu[g][j] = U_dia[j] - s;
    if (j < IN_SZ) {
        const float* Wu = sel4(g, Wu_f, Wu_i, Wu_c, Wu_o);
        const float* Wg = sel4(g, Wf, Wi, Wc, Wo);
        float sw = 0.f;
#pragma unroll 8
        for (int r = 0; r < R_SZ; ++r) sw += Wu[j * R_SZ + r] * Wg[r * H_SZ + j];
        g_aw[g][j] = W_dia[j] - sw;
    }
}

// ---------------- SGEMM with packed f32x2 FMA ----------------
// C tile: BM=128 x BN=64, BK=16, 256 threads, thread tile 8x4 (acc as 8x2 f32x2 pairs).
// colBlockStride/colOff let GEMM1 write into the gate-interleaved T layout directly.
__global__ __launch_bounds__(256)
void sgemm_f32x2(const float* __restrict__ A, int lda,
                 const float* __restrict__ Wm, int ldw,
                 float* __restrict__ C, int ldc,
                 int K, int colBlockStride, int colOff) {
    __shared__ float As[16][132];  // transposed A tile, padded
    __shared__ float Ws[16][64];

    const int tid = threadIdx.x;
    const int bx = blockIdx.x, by = blockIdx.y;

    const int tm = tid >> 4;          // 0..15
    const int tn = tid & 15;          // 0..15

    const int a_row = tid >> 2;       // 0..63
    const int a_k   = (tid & 3) << 2; // 0,4,8,12
    const int w_row = tid >> 4;       // 0..15
    const int w_col = (tid & 15) << 2;

    const float* Ag  = A + (size_t)(by * 128 + a_row) * lda + a_k;
    const float* Ag2 = Ag + (size_t)64 * lda;
    const float* Wg  = Wm + (size_t)w_row * ldw + bx * 64 + w_col;

    unsigned long long acc[8][2];
#pragma unroll
    for (int i = 0; i < 8; ++i) { acc[i][0] = 0ULL; acc[i][1] = 0ULL; }

    const int nkt = K >> 4;

    float4 a0 = *(const float4*)Ag;
    float4 a1 = *(const float4*)Ag2;
    float4 w0 = *(const float4*)Wg;

    for (int kt = 0; kt < nkt; ++kt) {
        As[a_k + 0][a_row]      = a0.x;
        As[a_k + 1][a_row]      = a0.y;
        As[a_k + 2][a_row]      = a0.z;
        As[a_k + 3][a_row]      = a0.w;
        As[a_k + 0][a_row + 64] = a1.x;
        As[a_k + 1][a_row + 64] = a1.y;
        As[a_k + 2][a_row + 64] = a1.z;
        As[a_k + 3][a_row + 64] = a1.w;
        *(float4*)&Ws[w_row][w_col] = w0;
        __syncthreads();

        if (kt + 1 < nkt) {
            a0 = *(const float4*)(Ag  + (size_t)(kt + 1) * 16);
            a1 = *(const float4*)(Ag2 + (size_t)(kt + 1) * 16);
            w0 = *(const float4*)(Wg  + (size_t)(kt + 1) * 16 * ldw);
        }

#pragma unroll
        for (int k = 0; k < 16; ++k) {
            float av[8];
            *(float4*)&av[0] = *(const float4*)&As[k][tm * 8];
            *(float4*)&av[4] = *(const float4*)&As[k][tm * 8 + 4];
            ulonglong2 bv = *(const ulonglong2*)&Ws[k][tn * 4];
#pragma unroll
            for (int i = 0; i < 8; ++i) {
                unsigned long long ap = pack2(av[i]);
                acc[i][0] = ffma2(ap, bv.x, acc[i][0]);
                acc[i][1] = ffma2(ap, bv.y, acc[i][1]);
            }
        }
        __syncthreads();
    }

    const int col = bx * colBlockStride + colOff + tn * 4;
    float* Cp = C + (size_t)(by * 128 + tm * 8) * ldc + col;
#pragma unroll
    for (int i = 0; i < 8; ++i) {
        float f0, f1, f2, f3;
        unpack2(acc[i][0], f0, f1);
        unpack2(acc[i][1], f2, f3);
        *(float4*)(Cp + (size_t)i * ldc) = make_float4(f0, f1, f2, f3);
    }
}

// ---------------- fused gate combine ----------------
__device__ __forceinline__ float sigf(float z) {
    z = fminf(fmaxf(z, -30.f), 30.f);
    return 1.f / (1.f + __expf(-z));
}
__device__ __forceinline__ float tanhfast(float z) {
    z = fminf(fmaxf(z, -15.f), 15.f);
    float e = __expf(-2.f * z);
    return (1.f - e) / (1.f + e);
}

__global__ __launch_bounds__(256)
void combine_kernel(const float* __restrict__ x, const float* __restrict__ h,
                    const float* __restrict__ c,
                    const float* __restrict__ bias_f, const float* __restrict__ bias_i,
                    const float* __restrict__ bias_c, const float* __restrict__ bias_o,
                    float* __restrict__ out) {
    int idx = blockIdx.x * blockDim.x + threadIdx.x;  // over B*H/4
    if (idx >= B_SZ * H_SZ / 4) return;
    int jq = idx & ((H_SZ / 4) - 1);
    int b  = idx >> 8;
    int j  = jq << 2;
    size_t base = ((size_t)b << 10) + j;
    const size_t GS = (size_t)B_SZ * H_SZ;

    float gf[4], gi[4], gc[4], go[4], hv[4], cv[4], xv[4];
    *(float4*)gf = *(const float4*)(g_G + base);
    *(float4*)gi = *(const float4*)(g_G + GS + base);
    *(float4*)gc = *(const float4*)(g_G + 2 * GS + base);
    *(float4*)go = *(const float4*)(g_G + 3 * GS + base);
    *(float4*)hv = *(const float4*)(h + base);
    *(float4*)cv = *(const float4*)(c + base);
    const bool hasx = (j < IN_SZ);
    if (hasx) *(float4*)xv = *(const float4*)(x + (size_t)b * IN_SZ + j);
    else { xv[0] = xv[1] = xv[2] = xv[3] = 0.f; }

    float bf[4], bi[4], bc[4], bo[4];
    *(float4*)bf = *(const float4*)(bias_f + j);
    *(float4*)bi = *(const float4*)(bias_i + j);
    *(float4*)bc = *(const float4*)(bias_c + j);
    *(float4*)bo = *(const float4*)(bias_o + j);

    float bu[4][4], aw[4][4];
#pragma unroll
    for (int g = 0; g < 4; ++g) {
        *(float4*)bu[g] = *(const float4*)&g_bu[g][j];
        if (hasx) *(float4*)aw[g] = *(const float4*)&g_aw[g][j];
        else { aw[g][0] = aw[g][1] = aw[g][2] = aw[g][3] = 0.f; }
    }

    float ho[4], co[4];
#pragma unroll
    for (int l = 0; l < 4; ++l) {
        float pf = gf[l] + bf[l] + hv[l] * bu[0][l] + xv[l] * aw[0][l];
        float pi = gi[l] + bi[l] + hv[l] * bu[1][l] + xv[l] * aw[1][l];
        float pc = gc[l] + bc[l] + hv[l] * bu[2][l] + xv[l] * aw[2][l];
        float po = go[l] + bo[l] + hv[l] * bu[3][l] + xv[l] * aw[3][l];
        float f  = sigf(pf);
        float ii = sigf(pi);
        float gg = tanhfast(pc);
        float o  = sigf(po);
        float cn = f * cv[l] + ii * gg;
        ho[l] = o * tanhfast(cn);
        co[l] = cn;
    }
    *(float4*)(out + base)      = *(float4*)ho;
    *(float4*)(out + GS + base) = *(float4*)co;
}

// ---------------- launch ----------------
extern "C" void kernel_launch(void* const* d_in, const int* in_sizes, int n_in,
                              void* d_out, int out_size) {
    const float* x = (const float*)d_in[0];
    const float* h = (const float*)d_in[1];
    const float* c = (const float*)d_in[2];
    const float* Wu_f = (const float*)d_in[3];
    const float* Wu_i = (const float*)d_in[4];
    const float* Wu_c = (const float*)d_in[5];
    const float* Wu_o = (const float*)d_in[6];
    const float* Uu_f = (const float*)d_in[7];
    const float* Uu_i = (const float*)d_in[8];
    const float* Uu_c = (const float*)d_in[9];
    const float* Uu_o = (const float*)d_in[10];
    const float* Wf = (const float*)d_in[11];
    const float* Wi = (const float*)d_in[12];
    const float* Wc = (const float*)d_in[13];
    const float* Wo = (const float*)d_in[14];
    const float* Uf = (const float*)d_in[15];
    const float* Ui = (const float*)d_in[16];
    const float* Uc = (const float*)d_in[17];
    const float* Uo = (const float*)d_in[18];
    const float* bias_f = (const float*)d_in[19];
    const float* bias_i = (const float*)d_in[20];
    const float* bias_c = (const float*)d_in[21];
    const float* bias_o = (const float*)d_in[22];
    const float* W_dia = (const float*)d_in[23];
    const float* U_dia = (const float*)d_in[24];
    float* out = (float*)d_out;

    float *pT, *pG, *pW1x, *pW1h, *pW2;
    cudaGetSymbolAddress((void**)&pT, g_T);
    cudaGetSymbolAddress((void**)&pG, g_G);
    cudaGetSymbolAddress((void**)&pW1x, g_W1x);
    cudaGetSymbolAddress((void**)&pW1h, g_W1h);
    cudaGetSymbolAddress((void**)&pW2, g_W2);

    prep_pack1<<<(H_SZ * 256 + 255) / 256, 256>>>(Wu_f, Wu_i, Wu_c, Wu_o, Uu_f, Uu_i, Uu_c, Uu_o);
    prep_pack2<<<(4 * 128 * H_SZ + 255) / 256, 256>>>(Wf, Wi, Wc, Wo, Uf, Ui, Uc, Uo);
    prep_diag<<<(4 * H_SZ + 255) / 256, 256>>>(Wu_f, Wu_i, Wu_c, Wu_o, Uu_f, Uu_i, Uu_c, Uu_o,
                                               Wf, Wi, Wc, Wo, Uf, Ui, Uc, Uo, W_dia, U_dia);

    // GEMM1: T[:, g*128 + 0..63]  = x @ Wu_g ; T[:, g*128 + 64..127] = h @ Uu_g
    sgemm_f32x2<<<dim3(4, B_SZ / 128), 256>>>(x, IN_SZ, pW1x, 256, pT, 512, IN_SZ, 128, 0);
    sgemm_f32x2<<<dim3(4, B_SZ / 128), 256>>>(h, H_SZ, pW1h, 256, pT, 512, H_SZ, 128, 64);

    // GEMM2 per gate: G_g = T[:, g*128:(g+1)*128] @ W2_g
    for (int g = 0; g < 4; ++g) {
        sgemm_f32x2<<<dim3(H_SZ / 64, B_SZ / 128), 256>>>(
            pT + g * 128, 512, pW2 + (size_t)g * 128 * H_SZ, H_SZ,
            pG + (size_t)g * B_SZ * H_SZ, H_SZ, 128, 64, 0);
    }

    combine_kernel<<<(B_SZ * H_SZ / 4) / 256, 256>>>(x, h, c, bias_f, bias_i, bias_c, bias_o, out);
}